// round 1
// baseline (speedup 1.0000x reference)
#include <cuda_runtime.h>
#include <cuda_bf16.h>

// ---------------- problem constants ----------------
#define T_    8192
#define D_    1024
#define DC_   256
#define E_    8
#define HID_  4096
#define CAP_  2560
#define NE_   7                 // router experts = E-1
#define SHOFF_ (E_*CAP_)        // 20480
#define RTOT_  (SHOFF_ + T_)    // 28672

// ---------------- scratch (device globals; no allocs allowed) ----------------
__device__ int   g_flat_e[T_*2];
__device__ float g_flat_w[T_*2];
__device__ int   g_tok_all[RTOT_];   // gr -> source token
__device__ int   g_tok2gr[T_*2];     // flat slot -> gr (or -1 if dropped)
__device__ int   g_cnt[E_+1];        // rows per segment (E routed + 1 shared)
__device__ float g_big[(size_t)RTOT_*HID_];  // ada (stride 3072) then h1 (stride 4096)
__device__ float g_hy [(size_t)RTOT_*D_];    // h_mod then y (=gate*h*mask)
__device__ float g_gate[(size_t)RTOT_*D_];

// ---------------- helpers ----------------
__device__ __forceinline__ unsigned long long packf2(float lo, float hi){
    unsigned long long r;
    asm("mov.b64 %0, {%1, %2};" : "=l"(r) : "f"(lo), "f"(hi));
    return r;
}
__device__ __forceinline__ void fma2(unsigned long long& d, unsigned long long a, unsigned long long b){
    asm("fma.rn.f32x2 %0, %1, %2, %3;" : "=l"(d) : "l"(a), "l"(b), "l"(d));
}
__device__ __forceinline__ float2 unpackf2(unsigned long long v){
    float2 f;
    asm("mov.b64 {%0, %1}, %2;" : "=f"(f.x), "=f"(f.y) : "l"(v));
    return f;
}
__device__ __forceinline__ float gelu_tanh(float x){
    // JAX default gelu (approximate=True)
    float x3 = x*x*x;
    return 0.5f*x*(1.0f + tanhf(0.7978845608028654f*(x + 0.044715f*x3)));
}

// ---------------- K1: router ----------------
__global__ void router_kernel(const float* __restrict__ x, const float* __restrict__ Wg){
    int t    = blockIdx.x*8 + (threadIdx.x>>5);
    int lane = threadIdx.x & 31;
    const float* xr = x + (size_t)t*D_;
    float s[NE_];
    #pragma unroll
    for (int j=0;j<NE_;j++) s[j]=0.f;
    for (int d=lane; d<D_; d+=32){
        float xv = xr[d];
        const float* wr = Wg + d*NE_;
        #pragma unroll
        for (int j=0;j<NE_;j++) s[j] += xv*wr[j];
    }
    #pragma unroll
    for (int o=16;o>0;o>>=1){
        #pragma unroll
        for (int j=0;j<NE_;j++) s[j] += __shfl_xor_sync(0xffffffffu, s[j], o);
    }
    if (lane==0){
        float mx = s[0];
        #pragma unroll
        for (int j=1;j<NE_;j++) mx = fmaxf(mx, s[j]);
        float p[NE_]; float sum=0.f;
        #pragma unroll
        for (int j=0;j<NE_;j++){ p[j]=expf(s[j]-mx); sum+=p[j]; }
        float inv = 1.f/sum;
        #pragma unroll
        for (int j=0;j<NE_;j++) p[j]*=inv;
        int i0=0; float p0=p[0];
        #pragma unroll
        for (int j=1;j<NE_;j++) if (p[j]>p0){p0=p[j]; i0=j;}
        int i1=-1; float p1=-1.f;
        #pragma unroll
        for (int j=0;j<NE_;j++) if (j!=i0 && p[j]>p1){p1=p[j]; i1=j;}
        float ws = p0+p1;
        g_flat_e[2*t]   = i0;  g_flat_e[2*t+1] = i1;
        g_flat_w[2*t]   = p0/ws;
        g_flat_w[2*t+1] = p1/ws;
    }
}

// ---------------- K2: stable binning (single block) ----------------
__global__ void bin_kernel(){
    __shared__ int hist[256][E_];
    const int tid = threadIdx.x;
    const int L = (T_*2)/256;           // 64
    const int lo = tid*L, hi = lo+L;
    int h[E_];
    #pragma unroll
    for (int e=0;e<E_;e++) h[e]=0;
    for (int i=lo;i<hi;i++) h[g_flat_e[i]]++;
    #pragma unroll
    for (int e=0;e<E_;e++) hist[tid][e]=h[e];
    __syncthreads();
    if (tid < E_){
        int run=0;
        for (int tt=0;tt<256;tt++){ int v=hist[tt][tid]; hist[tt][tid]=run; run+=v; }
        g_cnt[tid] = run < CAP_ ? run : CAP_;
    }
    if (tid == E_) g_cnt[E_] = T_;
    __syncthreads();
    int run[E_];
    #pragma unroll
    for (int e=0;e<E_;e++) run[e]=hist[tid][e];
    for (int i=lo;i<hi;i++){
        int e = g_flat_e[i];
        int rank = run[e]++;
        int gr = -1;
        if (rank < CAP_){ gr = e*CAP_ + rank; g_tok_all[gr] = i>>1; }
        g_tok2gr[i] = gr;
    }
    for (int t=tid; t<T_; t+=256) g_tok_all[SHOFF_+t] = t;   // shared segment identity
}

// ---------------- GEMM: C[M,N] = A[M,K] @ B[K,N] (+bias, epilogue) ----------------
// EPI: 0=ada store, 1=gelu->h1, 2=gate*y*mask -> y
// ASRC: 0=external A (param), 1=g_hy (h_mod), 2=g_big (h1)
template<int EPI, int ASRC, bool GATHER>
__global__ void __launch_bounds__(256,2) gemm_seg(
    const float* __restrict__ Aext, int K, int N,
    const float* __restrict__ Bw_e, const float* __restrict__ Bw_s,
    const float* __restrict__ bias_e, const float* __restrict__ bias_s,
    const float* __restrict__ mf, int z_off)
{
    const int e   = blockIdx.z + z_off;
    const int cnt = g_cnt[e];
    const int m0  = blockIdx.y*128;
    if (m0 >= cnt) return;
    const int row_off = (e < E_) ? e*CAP_ : SHOFF_;
    const float* Bw   = (e < E_) ? Bw_e   + (size_t)e*K*N : Bw_s;
    const float* bias = (e < E_) ? bias_e + (size_t)e*N   : bias_s;
    const float* Ap   = (ASRC==0) ? Aext : (ASRC==1) ? g_hy : g_big;
    float* Cp         = (EPI==2) ? g_hy : g_big;

    const int n0  = blockIdx.x*128;
    const int tid = threadIdx.x;
    __shared__ float As[8][128];
    __shared__ float Bs[8][128];

    // A loader: 128 rows x 8 k, one float4 per thread
    const int ar = tid>>1;
    const int ak = (tid&1)*4;
    int r_eff = m0 + ar; if (r_eff > cnt-1) r_eff = cnt-1;
    const float* Arow;
    if (GATHER) Arow = Ap + (size_t)g_tok_all[row_off + r_eff]*K;
    else        Arow = Ap + (size_t)(row_off + r_eff)*K;

    // B loader: 8 k x 128 cols, one float4 per thread
    const int bk = tid>>5;
    const int bn = (tid&31)*4;
    const float* Bbase = Bw + (size_t)bk*N + n0 + bn;

    const int ty = tid>>4, tx = tid&15;
    const int mrow = ty*8, ncol = tx*8;

    unsigned long long acc[8][4];
    #pragma unroll
    for (int i=0;i<8;i++)
        #pragma unroll
        for (int j=0;j<4;j++) acc[i][j]=0ull;

    const int Kt = K/8;
    float4 av = *(const float4*)(Arow + ak);
    float4 bv = *(const float4*)(Bbase);

    for (int kt=0;;){
        As[ak+0][ar]=av.x; As[ak+1][ar]=av.y; As[ak+2][ar]=av.z; As[ak+3][ar]=av.w;
        *(float4*)&Bs[bk][bn]=bv;
        __syncthreads();
        if (kt+1 < Kt){
            const int kb = (kt+1)*8;
            av = *(const float4*)(Arow + kb + ak);
            bv = *(const float4*)(Bbase + (size_t)kb*N);
        }
        #pragma unroll
        for (int k=0;k<8;k++){
            float4 a0 = *(const float4*)&As[k][mrow];
            float4 a1 = *(const float4*)&As[k][mrow+4];
            float4 b0 = *(const float4*)&Bs[k][ncol];
            float4 b1 = *(const float4*)&Bs[k][ncol+4];
            unsigned long long bp[4] = { packf2(b0.x,b0.y), packf2(b0.z,b0.w),
                                         packf2(b1.x,b1.y), packf2(b1.z,b1.w) };
            float aa[8] = {a0.x,a0.y,a0.z,a0.w,a1.x,a1.y,a1.z,a1.w};
            #pragma unroll
            for (int i=0;i<8;i++){
                unsigned long long apk = packf2(aa[i],aa[i]);
                #pragma unroll
                for (int j=0;j<4;j++) fma2(acc[i][j], apk, bp[j]);
            }
        }
        kt++;
        if (kt >= Kt) break;
        __syncthreads();
    }

    #pragma unroll
    for (int i=0;i<8;i++){
        const int r = m0 + mrow + i;
        if (r >= cnt) continue;
        const int gr = row_off + r;
        const size_t cbase = (size_t)gr*N + n0 + ncol;
        float msk = 1.f;
        if (EPI==2) msk = mf[g_tok_all[gr]];
        #pragma unroll
        for (int j=0;j<4;j++){
            float2 v = unpackf2(acc[i][j]);
            const int c0 = n0 + ncol + 2*j;
            float r0 = v.x + bias[c0];
            float r1 = v.y + bias[c0+1];
            if (EPI==0){
                Cp[cbase+2*j]   = r0;
                Cp[cbase+2*j+1] = r1;
            } else if (EPI==1){
                Cp[cbase+2*j]   = gelu_tanh(r0);
                Cp[cbase+2*j+1] = gelu_tanh(r1);
            } else {
                Cp[cbase+2*j]   = r0 * g_gate[cbase+2*j]   * msk;
                Cp[cbase+2*j+1] = r1 * g_gate[cbase+2*j+1] * msk;
            }
        }
    }
}

// ---------------- K4: LayerNorm + adaLN modulate ----------------
__global__ void hmod_kernel(const float* __restrict__ x){
    const int gr  = blockIdx.x;
    const int tid = threadIdx.x;
    if (gr < SHOFF_){
        int e = gr / CAP_;
        int r = gr - e*CAP_;
        if (r >= g_cnt[e]) return;          // padding rows: never read downstream
    }
    const int tok = g_tok_all[gr];
    const float* xr = x + (size_t)tok*D_;
    float s=0.f, ss=0.f;
    for (int c=tid;c<D_;c+=256){ float v=xr[c]; s+=v; ss+=v*v; }
    #pragma unroll
    for (int o=16;o>0;o>>=1){
        s  += __shfl_xor_sync(0xffffffffu, s, o);
        ss += __shfl_xor_sync(0xffffffffu, ss, o);
    }
    __shared__ float sw[8], ssw[8];
    __shared__ float mu_s, rstd_s;
    const int w = tid>>5;
    if ((tid&31)==0){ sw[w]=s; ssw[w]=ss; }
    __syncthreads();
    if (tid==0){
        float S=0.f, SS=0.f;
        #pragma unroll
        for (int i=0;i<8;i++){ S+=sw[i]; SS+=ssw[i]; }
        float mu  = S*(1.f/(float)D_);
        float var = SS*(1.f/(float)D_) - mu*mu;
        mu_s = mu; rstd_s = rsqrtf(var + 1e-5f);
    }
    __syncthreads();
    const float mu = mu_s, rstd = rstd_s;
    const float* ada = g_big + (size_t)gr*(3*D_);
    float* hm = g_hy   + (size_t)gr*D_;
    float* gt = g_gate + (size_t)gr*D_;
    for (int c=tid;c<D_;c+=256){
        float xn = (xr[c]-mu)*rstd;
        hm[c] = xn*(1.f + ada[D_+c]) + ada[c];
        gt[c] = ada[2*D_+c];
    }
}

// ---------------- K7: combine ----------------
__global__ void combine_kernel(float* __restrict__ out){
    const int idx = blockIdx.x*256 + threadIdx.x;
    const int t = idx >> 10;
    const int c = idx & (D_-1);
    float v = g_hy[(size_t)(SHOFF_+t)*D_ + c];   // shared expert output
    const int gr0 = g_tok2gr[2*t];
    const int gr1 = g_tok2gr[2*t+1];
    float m = 0.f;
    if (gr0 >= 0) m += g_flat_w[2*t]   * g_hy[(size_t)gr0*D_ + c];
    if (gr1 >= 0) m += g_flat_w[2*t+1] * g_hy[(size_t)gr1*D_ + c];
    out[idx] = (v + 2.f*m) * (1.f/3.f);
}

// ---------------- launch ----------------
extern "C" void kernel_launch(void* const* d_in, const int* in_sizes, int n_in,
                              void* d_out, int out_size)
{
    const float* x      = (const float*)d_in[0];
    const float* cond   = (const float*)d_in[1];
    const float* mask   = (const float*)d_in[2];
    const float* Wg     = (const float*)d_in[3];
    const float* Wada_s = (const float*)d_in[4];
    const float* bada_s = (const float*)d_in[5];
    const float* W1_s   = (const float*)d_in[6];
    const float* b1_s   = (const float*)d_in[7];
    const float* W2_s   = (const float*)d_in[8];
    const float* b2_s   = (const float*)d_in[9];
    const float* Wada_e = (const float*)d_in[10];
    const float* bada_e = (const float*)d_in[11];
    const float* W1_e   = (const float*)d_in[12];
    const float* b1_e   = (const float*)d_in[13];
    const float* W2_e   = (const float*)d_in[14];
    const float* b2_e   = (const float*)d_in[15];
    float* out = (float*)d_out;

    router_kernel<<<T_/8, 256>>>(x, Wg);
    bin_kernel<<<1, 256>>>();

    // ada = cond_gather @ Wada + bada   (K=256, N=3072)
    gemm_seg<0,0,true ><<<dim3(24,20,E_),256>>>(cond, DC_, 3*D_, Wada_e, Wada_s, bada_e, bada_s, nullptr, 0);
    gemm_seg<0,0,true ><<<dim3(24,64,1 ),256>>>(cond, DC_, 3*D_, Wada_e, Wada_s, bada_e, bada_s, nullptr, E_);

    hmod_kernel<<<RTOT_, 256>>>(x);

    // h1 = gelu(h_mod @ W1 + b1)        (K=1024, N=4096)
    gemm_seg<1,1,false><<<dim3(32,20,E_),256>>>(nullptr, D_, HID_, W1_e, W1_s, b1_e, b1_s, nullptr, 0);
    gemm_seg<1,1,false><<<dim3(32,64,1 ),256>>>(nullptr, D_, HID_, W1_e, W1_s, b1_e, b1_s, nullptr, E_);

    // y = gate * (h1 @ W2 + b2) * mask  (K=4096, N=1024)
    gemm_seg<2,2,false><<<dim3(8,20,E_),256>>>(nullptr, HID_, D_, W2_e, W2_s, b2_e, b2_s, mask, 0);
    gemm_seg<2,2,false><<<dim3(8,64,1 ),256>>>(nullptr, HID_, D_, W2_e, W2_s, b2_e, b2_s, mask, E_);

    combine_kernel<<<(T_*D_)/256, 256>>>(out);
}

// round 4
// speedup vs baseline: 2.5198x; 2.5198x over previous
#include <cuda_runtime.h>
#include <cuda_bf16.h>
#include <cstdint>

// ---------------- problem constants ----------------
#define T_    8192
#define D_    1024
#define DC_   256
#define E_    8
#define HID_  4096
#define CAP_  2560
#define NE_   7
#define SHOFF_ (E_*CAP_)        // 20480
#define RTOT_  (SHOFF_ + T_)    // 28672

// ---------------- scratch ----------------
__device__ int   g_flat_e[T_*2];
__device__ float g_flat_w[T_*2];
__device__ int   g_tok_all[RTOT_];
__device__ int   g_tok2gr[T_*2];
__device__ int   g_cnt[E_+1];
__device__ float g_big[(size_t)RTOT_*HID_];   // ada (stride 3072) then h1 (stride 4096)
__device__ float g_hy [(size_t)RTOT_*D_];     // h_mod then y
__device__ float g_gate[(size_t)RTOT_*D_];

// ---------------- helpers ----------------
__device__ __forceinline__ float totf32(float x){
    uint32_t u;
    asm("cvt.rn.tf32.f32 %0, %1;" : "=r"(u) : "f"(x));
    return __uint_as_float(u);
}
__device__ __forceinline__ float gelu_tanh(float x){
    float x3 = x*x*x;
    return 0.5f*x*(1.0f + tanhf(0.7978845608028654f*(x + 0.044715f*x3)));
}
__device__ __forceinline__ void mma_tf32(float* c, const uint32_t* a, const uint32_t* b){
    asm volatile("mma.sync.aligned.m16n8k8.row.col.f32.tf32.tf32.f32 "
                 "{%0,%1,%2,%3}, {%4,%5,%6,%7}, {%8,%9}, {%0,%1,%2,%3};"
                 : "+f"(c[0]), "+f"(c[1]), "+f"(c[2]), "+f"(c[3])
                 : "r"(a[0]), "r"(a[1]), "r"(a[2]), "r"(a[3]), "r"(b[0]), "r"(b[1]));
}

// ---------------- K1: router ----------------
__global__ void router_kernel(const float* __restrict__ x, const float* __restrict__ Wg){
    int t    = blockIdx.x*8 + (threadIdx.x>>5);
    int lane = threadIdx.x & 31;
    const float* xr = x + (size_t)t*D_;
    float s[NE_];
    #pragma unroll
    for (int j=0;j<NE_;j++) s[j]=0.f;
    for (int d=lane; d<D_; d+=32){
        float xv = xr[d];
        const float* wr = Wg + d*NE_;
        #pragma unroll
        for (int j=0;j<NE_;j++) s[j] += xv*wr[j];
    }
    #pragma unroll
    for (int o=16;o>0;o>>=1){
        #pragma unroll
        for (int j=0;j<NE_;j++) s[j] += __shfl_xor_sync(0xffffffffu, s[j], o);
    }
    if (lane==0){
        float mx = s[0];
        #pragma unroll
        for (int j=1;j<NE_;j++) mx = fmaxf(mx, s[j]);
        float p[NE_]; float sum=0.f;
        #pragma unroll
        for (int j=0;j<NE_;j++){ p[j]=expf(s[j]-mx); sum+=p[j]; }
        float inv = 1.f/sum;
        #pragma unroll
        for (int j=0;j<NE_;j++) p[j]*=inv;
        int i0=0; float p0=p[0];
        #pragma unroll
        for (int j=1;j<NE_;j++) if (p[j]>p0){p0=p[j]; i0=j;}
        int i1=-1; float p1=-1.f;
        #pragma unroll
        for (int j=0;j<NE_;j++) if (j!=i0 && p[j]>p1){p1=p[j]; i1=j;}
        float ws = p0+p1;
        g_flat_e[2*t]   = i0;  g_flat_e[2*t+1] = i1;
        g_flat_w[2*t]   = p0/ws;
        g_flat_w[2*t+1] = p1/ws;
    }
}

// ---------------- K2: stable binning (single block) ----------------
__global__ void bin_kernel(){
    __shared__ int hist[256][E_];
    const int tid = threadIdx.x;
    const int L = (T_*2)/256;
    const int lo = tid*L, hi = lo+L;
    int h[E_];
    #pragma unroll
    for (int e=0;e<E_;e++) h[e]=0;
    for (int i=lo;i<hi;i++) h[g_flat_e[i]]++;
    #pragma unroll
    for (int e=0;e<E_;e++) hist[tid][e]=h[e];
    __syncthreads();
    if (tid < E_){
        int run=0;
        for (int tt=0;tt<256;tt++){ int v=hist[tt][tid]; hist[tt][tid]=run; run+=v; }
        g_cnt[tid] = run < CAP_ ? run : CAP_;
    }
    if (tid == E_) g_cnt[E_] = T_;
    __syncthreads();
    int run[E_];
    #pragma unroll
    for (int e=0;e<E_;e++) run[e]=hist[tid][e];
    for (int i=lo;i<hi;i++){
        int e = g_flat_e[i];
        int rank = run[e]++;
        int gr = -1;
        if (rank < CAP_){ gr = e*CAP_ + rank; g_tok_all[gr] = i>>1; }
        g_tok2gr[i] = gr;
    }
    for (int t=tid; t<T_; t+=256) g_tok_all[SHOFF_+t] = t;
}

// ---------------- GEMM via mma.sync tf32: C[M,N] = A[M,K] @ B[K,N] ----------------
// EPI: 0=ada store, 1=gelu->h1, 2=gate*y*mask -> y
// ASRC: 0=external A (param), 1=g_hy (h_mod), 2=g_big (h1)
// B is [K,N] row-major (original weight layout).
template<int EPI, int ASRC, bool GATHER>
__global__ void __launch_bounds__(256) gemm_mma(
    const float* __restrict__ Aext, int K, int N,
    const float* __restrict__ Bw_e, const float* __restrict__ Bw_s,
    const float* __restrict__ bias_e, const float* __restrict__ bias_s,
    const float* __restrict__ mf, int z_off)
{
    const int e   = blockIdx.z + z_off;
    const int cnt = g_cnt[e];
    const int m0  = blockIdx.y*128;
    if (m0 >= cnt) return;
    const int row_off = (e < E_) ? e*CAP_ : SHOFF_;
    const float* Bw   = (e < E_) ? Bw_e   + (size_t)e*K*N : Bw_s;
    const float* bias = (e < E_) ? bias_e + (size_t)e*N   : bias_s;
    const float* Ap   = (ASRC==0) ? Aext : (ASRC==1) ? g_hy : g_big;
    float* Cp         = (EPI==2) ? g_hy : g_big;

    const int n0  = blockIdx.x*128;
    const int tid = threadIdx.x;
    const int lane = tid&31, wid = tid>>5;

    __shared__ float As[16][136];   // [k][m], stride 136 -> conflict-free frags
    __shared__ float Bs[16][136];   // [k][n]

    // A loader: thread -> row = tid>>1 (0..127), kbase = (tid&1)*8, 8 k's via 2 float4
    const int ar = tid>>1, akb = (tid&1)*8;
    int r_eff = m0 + ar; if (r_eff > cnt-1) r_eff = cnt-1;
    const float* Arow;
    if (GATHER) Arow = Ap + (size_t)g_tok_all[row_off + r_eff]*K + akb;
    else        Arow = Ap + (size_t)(row_off + r_eff)*K + akb;

    // B loader: k = tid>>5 (and +8), n = (tid&31)*4, 2 float4
    const int bk = tid>>5, bn = (tid&31)*4;
    const float* Bb = Bw + (size_t)bk*N + n0 + bn;

    // warp tile: 2 (M) x 4 (N) warps; each warp 64x32
    const int wm = (wid>>2)*64, wn = (wid&3)*32;
    const int g = lane>>2, tg = lane&3;

    float acc[4][4][4];
    #pragma unroll
    for (int mt=0;mt<4;mt++)
        #pragma unroll
        for (int nt=0;nt<4;nt++)
            #pragma unroll
            for (int i=0;i<4;i++) acc[mt][nt][i]=0.f;

    const int KT = K/16;
    float4 av0 = *(const float4*)(Arow);
    float4 av1 = *(const float4*)(Arow+4);
    float4 bv0 = *(const float4*)(Bb);
    float4 bv1 = *(const float4*)(Bb + (size_t)8*N);

    for (int kt=0;;){
        As[akb+0][ar]=totf32(av0.x); As[akb+1][ar]=totf32(av0.y);
        As[akb+2][ar]=totf32(av0.z); As[akb+3][ar]=totf32(av0.w);
        As[akb+4][ar]=totf32(av1.x); As[akb+5][ar]=totf32(av1.y);
        As[akb+6][ar]=totf32(av1.z); As[akb+7][ar]=totf32(av1.w);
        *(float4*)&Bs[bk  ][bn] = make_float4(totf32(bv0.x),totf32(bv0.y),totf32(bv0.z),totf32(bv0.w));
        *(float4*)&Bs[bk+8][bn] = make_float4(totf32(bv1.x),totf32(bv1.y),totf32(bv1.z),totf32(bv1.w));
        __syncthreads();
        if (kt+1 < KT){
            const int kb = (kt+1)*16;
            av0 = *(const float4*)(Arow + kb);
            av1 = *(const float4*)(Arow + kb + 4);
            bv0 = *(const float4*)(Bb + (size_t)kb*N);
            bv1 = *(const float4*)(Bb + (size_t)(kb+8)*N);
        }
        #pragma unroll
        for (int kk=0;kk<16;kk+=8){
            uint32_t a[4][4], b[4][2];
            #pragma unroll
            for (int mt=0;mt<4;mt++){
                const int m = wm + mt*16 + g;
                a[mt][0]=__float_as_uint(As[kk+tg  ][m]);
                a[mt][1]=__float_as_uint(As[kk+tg  ][m+8]);
                a[mt][2]=__float_as_uint(As[kk+tg+4][m]);
                a[mt][3]=__float_as_uint(As[kk+tg+4][m+8]);
            }
            #pragma unroll
            for (int nt=0;nt<4;nt++){
                const int n = wn + nt*8 + g;
                b[nt][0]=__float_as_uint(Bs[kk+tg  ][n]);
                b[nt][1]=__float_as_uint(Bs[kk+tg+4][n]);
            }
            #pragma unroll
            for (int mt=0;mt<4;mt++)
                #pragma unroll
                for (int nt=0;nt<4;nt++)
                    mma_tf32(acc[mt][nt], a[mt], b[nt]);
        }
        kt++;
        if (kt >= KT) break;
        __syncthreads();
    }

    // epilogue: c0,c1 at (row g, col 2*tg..+1), c2,c3 at (row g+8)
    #pragma unroll
    for (int mt=0;mt<4;mt++){
        #pragma unroll
        for (int half=0;half<2;half++){
            const int r = m0 + wm + mt*16 + g + half*8;
            if (r >= cnt) continue;
            const int gr = row_off + r;
            float msk = 1.f;
            if (EPI==2) msk = mf[g_tok_all[gr]];
            #pragma unroll
            for (int nt=0;nt<4;nt++){
                const int c = n0 + wn + nt*8 + 2*tg;
                float v0 = acc[mt][nt][half*2+0] + bias[c];
                float v1 = acc[mt][nt][half*2+1] + bias[c+1];
                if (EPI==1){ v0 = gelu_tanh(v0); v1 = gelu_tanh(v1); }
                if (EPI==2){
                    v0 = v0 * g_gate[(size_t)gr*N + c]   * msk;
                    v1 = v1 * g_gate[(size_t)gr*N + c+1] * msk;
                }
                *(float2*)&Cp[(size_t)gr*N + c] = make_float2(v0, v1);
            }
        }
    }
}

// ---------------- K4: LayerNorm + adaLN modulate ----------------
__global__ void hmod_kernel(const float* __restrict__ x){
    const int gr  = blockIdx.x;
    const int tid = threadIdx.x;
    if (gr < SHOFF_){
        int e = gr / CAP_;
        if ((gr - e*CAP_) >= g_cnt[e]) return;
    }
    const int tok = g_tok_all[gr];
    const float* xr = x + (size_t)tok*D_;
    float s=0.f, ss=0.f;
    for (int c=tid;c<D_;c+=256){ float v=xr[c]; s+=v; ss+=v*v; }
    #pragma unroll
    for (int o=16;o>0;o>>=1){
        s  += __shfl_xor_sync(0xffffffffu, s, o);
        ss += __shfl_xor_sync(0xffffffffu, ss, o);
    }
    __shared__ float sw[8], ssw[8];
    __shared__ float mu_s, rstd_s;
    const int w = tid>>5;
    if ((tid&31)==0){ sw[w]=s; ssw[w]=ss; }
    __syncthreads();
    if (tid==0){
        float S=0.f, SS=0.f;
        #pragma unroll
        for (int i=0;i<8;i++){ S+=sw[i]; SS+=ssw[i]; }
        float mu  = S*(1.f/(float)D_);
        float var = SS*(1.f/(float)D_) - mu*mu;
        mu_s = mu; rstd_s = rsqrtf(var + 1e-5f);
    }
    __syncthreads();
    const float mu = mu_s, rstd = rstd_s;
    const float* ada = g_big + (size_t)gr*(3*D_);
    float* hm = g_hy   + (size_t)gr*D_;
    float* gt = g_gate + (size_t)gr*D_;
    for (int c=tid;c<D_;c+=256){
        float xn = (xr[c]-mu)*rstd;
        hm[c] = xn*(1.f + ada[D_+c]) + ada[c];
        gt[c] = ada[2*D_+c];
    }
}

// ---------------- K7: combine ----------------
__global__ void combine_kernel(float* __restrict__ out){
    const int idx = blockIdx.x*256 + threadIdx.x;
    const int t = idx >> 10;
    const int c = idx & (D_-1);
    float v = g_hy[(size_t)(SHOFF_+t)*D_ + c];
    const int gr0 = g_tok2gr[2*t];
    const int gr1 = g_tok2gr[2*t+1];
    float m = 0.f;
    if (gr0 >= 0) m += g_flat_w[2*t]   * g_hy[(size_t)gr0*D_ + c];
    if (gr1 >= 0) m += g_flat_w[2*t+1] * g_hy[(size_t)gr1*D_ + c];
    out[idx] = (v + 2.f*m) * (1.f/3.f);
}

// ---------------- launch ----------------
extern "C" void kernel_launch(void* const* d_in, const int* in_sizes, int n_in,
                              void* d_out, int out_size)
{
    const float* x      = (const float*)d_in[0];
    const float* cond   = (const float*)d_in[1];
    const float* mask   = (const float*)d_in[2];
    const float* Wg     = (const float*)d_in[3];
    const float* Wada_s = (const float*)d_in[4];
    const float* bada_s = (const float*)d_in[5];
    const float* W1_s   = (const float*)d_in[6];
    const float* b1_s   = (const float*)d_in[7];
    const float* W2_s   = (const float*)d_in[8];
    const float* b2_s   = (const float*)d_in[9];
    const float* Wada_e = (const float*)d_in[10];
    const float* bada_e = (const float*)d_in[11];
    const float* W1_e   = (const float*)d_in[12];
    const float* b1_e   = (const float*)d_in[13];
    const float* W2_e   = (const float*)d_in[14];
    const float* b2_e   = (const float*)d_in[15];
    float* out = (float*)d_out;

    router_kernel<<<T_/8, 256>>>(x, Wg);
    bin_kernel<<<1, 256>>>();

    // ada = cond_gather @ Wada + bada   (K=256, N=3072)
    gemm_mma<0,0,true ><<<dim3(24,20,E_),256>>>(cond, DC_, 3*D_, Wada_e, Wada_s, bada_e, bada_s, nullptr, 0);
    gemm_mma<0,0,true ><<<dim3(24,64,1 ),256>>>(cond, DC_, 3*D_, Wada_e, Wada_s, bada_e, bada_s, nullptr, E_);

    hmod_kernel<<<RTOT_, 256>>>(x);

    // h1 = gelu(h_mod @ W1 + b1)        (K=1024, N=4096)
    gemm_mma<1,1,false><<<dim3(32,20,E_),256>>>(nullptr, D_, HID_, W1_e, W1_s, b1_e, b1_s, nullptr, 0);
    gemm_mma<1,1,false><<<dim3(32,64,1 ),256>>>(nullptr, D_, HID_, W1_e, W1_s, b1_e, b1_s, nullptr, E_);

    // y = gate * (h1 @ W2 + b2) * mask  (K=4096, N=1024)
    gemm_mma<2,2,false><<<dim3(8,20,E_),256>>>(nullptr, HID_, W2_e ? D_ : D_, W2_e, W2_s, b2_e, b2_s, mask, 0);
    gemm_mma<2,2,false><<<dim3(8,64,1 ),256>>>(nullptr, HID_, D_, W2_e, W2_s, b2_e, b2_s, mask, E_);

    combine_kernel<<<(T_*D_)/256, 256>>>(out);
}

// round 9
// speedup vs baseline: 2.8036x; 1.1126x over previous
#include <cuda_runtime.h>
#include <cuda_bf16.h>
#include <cstdint>

// ---------------- problem constants ----------------
#define T_    8192
#define D_    1024
#define DC_   256
#define E_    8
#define HID_  4096
#define CAP_  2560
#define NE_   7
#define SHOFF_ (E_*CAP_)        // 20480
#define RTOT_  (SHOFF_ + T_)    // 28672

// GEMM tiling
#define BM 128
#define BN 128
#define BK 16
#define ASTRIDE 20              // floats, conflict-free A frag reads
#define BSTRIDE 136             // floats, conflict-free B frag reads
#define AS_BYTES (BM*ASTRIDE*4)     // 10240
#define BS_BYTES (BK*BSTRIDE*4)     // 8704
#define STAGE_BYTES (AS_BYTES + BS_BYTES)   // 18944
#define NSTAGE 3
#define SMEM_TOTAL (NSTAGE*STAGE_BYTES)     // 56832

// ---------------- scratch ----------------
__device__ int   g_flat_e[T_*2];
__device__ float g_flat_w[T_*2];
__device__ int   g_tok_all[RTOT_];
__device__ int   g_tok2gr[T_*2];
__device__ int   g_cnt[E_+1];
__device__ float g_big[(size_t)RTOT_*HID_];   // ada (stride 3072) then h1 (stride 4096)
__device__ float g_hy [(size_t)RTOT_*D_];     // h_mod then y
__device__ float g_gate[(size_t)RTOT_*D_];
__device__ float g_condg[(size_t)RTOT_*DC_];  // gathered + tf32-rounded cond

// ---------------- helpers ----------------
__device__ __forceinline__ uint32_t smem_u32(const void* p){
    uint32_t a;
    asm("{ .reg .u64 t; cvta.to.shared.u64 t, %1; cvt.u32.u64 %0, t; }" : "=r"(a) : "l"(p));
    return a;
}
__device__ __forceinline__ float totf32(float x){
    uint32_t u;
    asm("cvt.rn.tf32.f32 %0, %1;" : "=r"(u) : "f"(x));
    return __uint_as_float(u);
}
__device__ __forceinline__ uint32_t totf32u(float x){
    uint32_t u;
    asm("cvt.rn.tf32.f32 %0, %1;" : "=r"(u) : "f"(x));
    return u;
}
__device__ __forceinline__ float gelu_tanh(float x){
    float x3 = x*x*x;
    return 0.5f*x*(1.0f + tanhf(0.7978845608028654f*(x + 0.044715f*x3)));
}
__device__ __forceinline__ void cp16(uint32_t dst, const void* src){
    asm volatile("cp.async.cg.shared.global [%0], [%1], 16;" :: "r"(dst), "l"(src) : "memory");
}
__device__ __forceinline__ void cp_commit(){
    asm volatile("cp.async.commit_group;" ::: "memory");
}
__device__ __forceinline__ void mma_tf32(float* c, const uint32_t* a, const uint32_t* b){
    asm volatile("mma.sync.aligned.m16n8k8.row.col.f32.tf32.tf32.f32 "
                 "{%0,%1,%2,%3}, {%4,%5,%6,%7}, {%8,%9}, {%0,%1,%2,%3};"
                 : "+f"(c[0]), "+f"(c[1]), "+f"(c[2]), "+f"(c[3])
                 : "r"(a[0]), "r"(a[1]), "r"(a[2]), "r"(a[3]), "r"(b[0]), "r"(b[1]));
}

// ---------------- K1: router ----------------
__global__ void router_kernel(const float* __restrict__ x, const float* __restrict__ Wg){
    int t    = blockIdx.x*8 + (threadIdx.x>>5);
    int lane = threadIdx.x & 31;
    const float* xr = x + (size_t)t*D_;
    float s[NE_];
    #pragma unroll
    for (int j=0;j<NE_;j++) s[j]=0.f;
    for (int d=lane; d<D_; d+=32){
        float xv = xr[d];
        const float* wr = Wg + d*NE_;
        #pragma unroll
        for (int j=0;j<NE_;j++) s[j] += xv*wr[j];
    }
    #pragma unroll
    for (int o=16;o>0;o>>=1){
        #pragma unroll
        for (int j=0;j<NE_;j++) s[j] += __shfl_xor_sync(0xffffffffu, s[j], o);
    }
    if (lane==0){
        float mx = s[0];
        #pragma unroll
        for (int j=1;j<NE_;j++) mx = fmaxf(mx, s[j]);
        float p[NE_]; float sum=0.f;
        #pragma unroll
        for (int j=0;j<NE_;j++){ p[j]=expf(s[j]-mx); sum+=p[j]; }
        float inv = 1.f/sum;
        #pragma unroll
        for (int j=0;j<NE_;j++) p[j]*=inv;
        int i0=0; float p0=p[0];
        #pragma unroll
        for (int j=1;j<NE_;j++) if (p[j]>p0){p0=p[j]; i0=j;}
        int i1=-1; float p1=-1.f;
        #pragma unroll
        for (int j=0;j<NE_;j++) if (j!=i0 && p[j]>p1){p1=p[j]; i1=j;}
        float ws = p0+p1;
        g_flat_e[2*t]   = i0;  g_flat_e[2*t+1] = i1;
        g_flat_w[2*t]   = p0/ws;
        g_flat_w[2*t+1] = p1/ws;
    }
}

// ---------------- K2: stable binning (single block) ----------------
__global__ void bin_kernel(){
    __shared__ int hist[256][E_];
    const int tid = threadIdx.x;
    const int L = (T_*2)/256;
    const int lo = tid*L, hi = lo+L;
    int h[E_];
    #pragma unroll
    for (int e=0;e<E_;e++) h[e]=0;
    for (int i=lo;i<hi;i++) h[g_flat_e[i]]++;
    #pragma unroll
    for (int e=0;e<E_;e++) hist[tid][e]=h[e];
    __syncthreads();
    if (tid < E_){
        int run=0;
        for (int tt=0;tt<256;tt++){ int v=hist[tt][tid]; hist[tt][tid]=run; run+=v; }
        g_cnt[tid] = run < CAP_ ? run : CAP_;
    }
    if (tid == E_) g_cnt[E_] = T_;
    __syncthreads();
    int run[E_];
    #pragma unroll
    for (int e=0;e<E_;e++) run[e]=hist[tid][e];
    for (int i=lo;i<hi;i++){
        int e = g_flat_e[i];
        int rank = run[e]++;
        int gr = -1;
        if (rank < CAP_){ gr = e*CAP_ + rank; g_tok_all[gr] = i>>1; }
        g_tok2gr[i] = gr;
    }
    for (int t=tid; t<T_; t+=256) g_tok_all[SHOFF_+t] = t;
}

// ---------------- K3: gather cond (tf32-rounded), rows become contiguous ----------------
__global__ void gather_cond_kernel(const float* __restrict__ cond){
    int gr = blockIdx.x;
    if (gr < SHOFF_){ int e = gr/CAP_; if ((gr - e*CAP_) >= g_cnt[e]) return; }
    int tok = g_tok_all[gr];
    const float4* src = (const float4*)(cond + (size_t)tok*DC_);
    float4* dst = (float4*)(g_condg + (size_t)gr*DC_);
    float4 v = src[threadIdx.x];
    v.x=totf32(v.x); v.y=totf32(v.y); v.z=totf32(v.z); v.w=totf32(v.w);
    dst[threadIdx.x] = v;
}

// ---------------- GEMM via mma.sync tf32, 3-stage cp.async pipeline ----------------
// C[M,N] = A[M,K] @ B[K,N] + bias, epilogue variants.
// EPI: 0=ada raw store, 1=tf32(gelu)->h1, 2=*gate*mask -> y
// ASRC: 0=g_condg, 1=g_hy (h_mod, pre-rounded), 2=g_big (h1, pre-rounded)
template<int EPI, int ASRC>
__global__ void __launch_bounds__(256,2) gemm_mma(
    int K, int N,
    const float* __restrict__ Bw_e, const float* __restrict__ Bw_s,
    const float* __restrict__ bias_e, const float* __restrict__ bias_s,
    const float* __restrict__ mf)
{
    const int e   = blockIdx.z;
    const int cnt = g_cnt[e];
    const int m0  = blockIdx.y*BM;
    if (m0 >= cnt) return;
    const int row_off = (e < E_) ? e*CAP_ : SHOFF_;
    const float* Bw   = (e < E_) ? Bw_e   + (size_t)e*K*N : Bw_s;
    const float* bias = (e < E_) ? bias_e + (size_t)e*N   : bias_s;
    const float* Ap   = (ASRC==0) ? g_condg : (ASRC==1) ? g_hy : g_big;
    float* Cp         = (EPI==2) ? g_hy : g_big;

    const int n0  = blockIdx.x*BN;
    const int tid = threadIdx.x;
    const int lane = tid&31, wid = tid>>5;

    extern __shared__ char smem[];
    const uint32_t sbase = smem_u32(smem);

    // A loader: row = tid>>1, koff = (tid&1)*8 -> two cp16
    const int ar = tid>>1, akb = (tid&1)*8;
    int r_eff = m0 + ar; if (r_eff > cnt-1) r_eff = cnt-1;
    const float* Arow = Ap + (size_t)(row_off + r_eff)*K + akb;
    const uint32_t aDst = sbase + (uint32_t)(ar*ASTRIDE + akb)*4u;

    // B loader: k = tid>>5 (and +8), n = (tid&31)*4 -> two cp16
    const int bk = tid>>5, bn = (tid&31)*4;
    const float* Bb = Bw + (size_t)bk*N + n0 + bn;
    const uint32_t bDst = sbase + AS_BYTES + (uint32_t)(bk*BSTRIDE + bn)*4u;

    // warp tile: 2 (M) x 4 (N) warps; each warp 64x32
    const int wm = (wid>>2)*64, wn = (wid&3)*32;
    const int g = lane>>2, tg = lane&3;

    float acc[4][4][4];
    #pragma unroll
    for (int mt=0;mt<4;mt++)
        #pragma unroll
        for (int nt=0;nt<4;nt++)
            #pragma unroll
            for (int i=0;i<4;i++) acc[mt][nt][i]=0.f;

    const int KT = K/BK;

    // prologue: stages 0,1
    #pragma unroll
    for (int s=0;s<2;s++){
        const uint32_t so = s*STAGE_BYTES;
        const float* Ag = Arow + s*BK;
        const float* Bg = Bb   + (size_t)s*BK*N;
        cp16(aDst+so,      Ag);
        cp16(aDst+so+16,   Ag+4);
        cp16(bDst+so,      Bg);
        cp16(bDst+so+(uint32_t)8*BSTRIDE*4, Bg + (size_t)8*N);
        cp_commit();
    }

    for (int kt=0; kt<KT; kt++){
        if (kt+1<KT) asm volatile("cp.async.wait_group 1;" ::: "memory");
        else         asm volatile("cp.async.wait_group 0;" ::: "memory");
        __syncthreads();
        if (kt+2<KT){
            const int s2 = (kt+2)%NSTAGE;
            const uint32_t so = s2*STAGE_BYTES;
            const float* Ag = Arow + (kt+2)*BK;
            const float* Bg = Bb   + (size_t)(kt+2)*BK*N;
            cp16(aDst+so,      Ag);
            cp16(aDst+so+16,   Ag+4);
            cp16(bDst+so,      Bg);
            cp16(bDst+so+(uint32_t)8*BSTRIDE*4, Bg + (size_t)8*N);
            cp_commit();
        }
        const float* As_ = (const float*)(smem + (kt%NSTAGE)*STAGE_BYTES);
        const float* Bs_ = As_ + BM*ASTRIDE;
        #pragma unroll
        for (int kk=0;kk<BK;kk+=8){
            uint32_t a[4][4], b[4][2];
            #pragma unroll
            for (int mt=0;mt<4;mt++){
                const int m = wm + mt*16 + g;
                a[mt][0]=__float_as_uint(As_[(size_t)m    *ASTRIDE + kk+tg  ]);
                a[mt][1]=__float_as_uint(As_[(size_t)(m+8)*ASTRIDE + kk+tg  ]);
                a[mt][2]=__float_as_uint(As_[(size_t)m    *ASTRIDE + kk+tg+4]);
                a[mt][3]=__float_as_uint(As_[(size_t)(m+8)*ASTRIDE + kk+tg+4]);
            }
            #pragma unroll
            for (int nt=0;nt<4;nt++){
                const int n = wn + nt*8 + g;
                b[nt][0]=totf32u(Bs_[(size_t)(kk+tg  )*BSTRIDE + n]);
                b[nt][1]=totf32u(Bs_[(size_t)(kk+tg+4)*BSTRIDE + n]);
            }
            #pragma unroll
            for (int mt=0;mt<4;mt++)
                #pragma unroll
                for (int nt=0;nt<4;nt++)
                    mma_tf32(acc[mt][nt], a[mt], b[nt]);
        }
        __syncthreads();
    }

    // epilogue
    #pragma unroll
    for (int mt=0;mt<4;mt++){
        #pragma unroll
        for (int half=0;half<2;half++){
            const int r = m0 + wm + mt*16 + g + half*8;
            if (r >= cnt) continue;
            const int gr = row_off + r;
            float msk = 1.f;
            if (EPI==2) msk = mf[g_tok_all[gr]];
            #pragma unroll
            for (int nt=0;nt<4;nt++){
                const int c = n0 + wn + nt*8 + 2*tg;
                float v0 = acc[mt][nt][half*2+0] + bias[c];
                float v1 = acc[mt][nt][half*2+1] + bias[c+1];
                if (EPI==1){ v0 = totf32(gelu_tanh(v0)); v1 = totf32(gelu_tanh(v1)); }
                if (EPI==2){
                    v0 = v0 * g_gate[(size_t)gr*N + c]   * msk;
                    v1 = v1 * g_gate[(size_t)gr*N + c+1] * msk;
                }
                *(float2*)&Cp[(size_t)gr*N + c] = make_float2(v0, v1);
            }
        }
    }
}

// ---------------- K4: LayerNorm + adaLN modulate (h_mod pre-rounded) ----------------
__global__ void hmod_kernel(const float* __restrict__ x){
    const int gr  = blockIdx.x;
    const int tid = threadIdx.x;
    if (gr < SHOFF_){
        int e = gr / CAP_;
        if ((gr - e*CAP_) >= g_cnt[e]) return;
    }
    const int tok = g_tok_all[gr];
    const float* xr = x + (size_t)tok*D_;
    float s=0.f, ss=0.f;
    for (int c=tid;c<D_;c+=256){ float v=xr[c]; s+=v; ss+=v*v; }
    #pragma unroll
    for (int o=16;o>0;o>>=1){
        s  += __shfl_xor_sync(0xffffffffu, s, o);
        ss += __shfl_xor_sync(0xffffffffu, ss, o);
    }
    __shared__ float sw[8], ssw[8];
    __shared__ float mu_s, rstd_s;
    const int w = tid>>5;
    if ((tid&31)==0){ sw[w]=s; ssw[w]=ss; }
    __syncthreads();
    if (tid==0){
        float S=0.f, SS=0.f;
        #pragma unroll
        for (int i=0;i<8;i++){ S+=sw[i]; SS+=ssw[i]; }
        float mu  = S*(1.f/(float)D_);
        float var = SS*(1.f/(float)D_) - mu*mu;
        mu_s = mu; rstd_s = rsqrtf(var + 1e-5f);
    }
    __syncthreads();
    const float mu = mu_s, rstd = rstd_s;
    const float* ada = g_big + (size_t)gr*(3*D_);
    float* hm = g_hy   + (size_t)gr*D_;
    float* gt = g_gate + (size_t)gr*D_;
    for (int c=tid;c<D_;c+=256){
        float xn = (xr[c]-mu)*rstd;
        hm[c] = totf32(xn*(1.f + ada[D_+c]) + ada[c]);
        gt[c] = ada[2*D_+c];
    }
}

// ---------------- K7: combine ----------------
__global__ void combine_kernel(float* __restrict__ out){
    const int idx = blockIdx.x*256 + threadIdx.x;
    const int t = idx >> 10;
    const int c = idx & (D_-1);
    float v = g_hy[(size_t)(SHOFF_+t)*D_ + c];
    const int gr0 = g_tok2gr[2*t];
    const int gr1 = g_tok2gr[2*t+1];
    float m = 0.f;
    if (gr0 >= 0) m += g_flat_w[2*t]   * g_hy[(size_t)gr0*D_ + c];
    if (gr1 >= 0) m += g_flat_w[2*t+1] * g_hy[(size_t)gr1*D_ + c];
    out[idx] = (v + 2.f*m) * (1.f/3.f);
}

// ---------------- launch ----------------
extern "C" void kernel_launch(void* const* d_in, const int* in_sizes, int n_in,
                              void* d_out, int out_size)
{
    const float* x      = (const float*)d_in[0];
    const float* cond   = (const float*)d_in[1];
    const float* mask   = (const float*)d_in[2];
    const float* Wg     = (const float*)d_in[3];
    const float* Wada_s = (const float*)d_in[4];
    const float* bada_s = (const float*)d_in[5];
    const float* W1_s   = (const float*)d_in[6];
    const float* b1_s   = (const float*)d_in[7];
    const float* W2_s   = (const float*)d_in[8];
    const float* b2_s   = (const float*)d_in[9];
    const float* Wada_e = (const float*)d_in[10];
    const float* bada_e = (const float*)d_in[11];
    const float* W1_e   = (const float*)d_in[12];
    const float* b1_e   = (const float*)d_in[13];
    const float* W2_e   = (const float*)d_in[14];
    const float* b2_e   = (const float*)d_in[15];
    float* out = (float*)d_out;

    cudaFuncSetAttribute(gemm_mma<0,0>, cudaFuncAttributeMaxDynamicSharedMemorySize, SMEM_TOTAL);
    cudaFuncSetAttribute(gemm_mma<1,1>, cudaFuncAttributeMaxDynamicSharedMemorySize, SMEM_TOTAL);
    cudaFuncSetAttribute(gemm_mma<2,2>, cudaFuncAttributeMaxDynamicSharedMemorySize, SMEM_TOTAL);

    router_kernel<<<T_/8, 256>>>(x, Wg);
    bin_kernel<<<1, 256>>>();
    gather_cond_kernel<<<RTOT_, 64>>>(cond);

    // ada = cond_g @ Wada + bada   (K=256, N=3072)
    gemm_mma<0,0><<<dim3(24,64,9),256,SMEM_TOTAL>>>(DC_, 3*D_, Wada_e, Wada_s, bada_e, bada_s, nullptr);

    hmod_kernel<<<RTOT_, 256>>>(x);

    // h1 = tf32(gelu(h_mod @ W1 + b1))   (K=1024, N=4096)
    gemm_mma<1,1><<<dim3(32,64,9),256,SMEM_TOTAL>>>(D_, HID_, W1_e, W1_s, b1_e, b1_s, nullptr);

    // y = (h1 @ W2 + b2) * gate * mask   (K=4096, N=1024)
    gemm_mma<2,2><<<dim3(8,64,9),256,SMEM_TOTAL>>>(HID_, D_, W2_e, W2_s, b2_e, b2_s, mask);

    combine_kernel<<<(T_*D_)/256, 256>>>(out);
}

// round 17
// speedup vs baseline: 2.8245x; 1.0075x over previous
#include <cuda_runtime.h>
#include <cuda_bf16.h>
#include <cstdint>

// ---------------- problem constants ----------------
#define T_    8192
#define D_    1024
#define DC_   256
#define E_    8
#define HID_  4096
#define CAP_  2560
#define NE_   7
#define SHOFF_ (E_*CAP_)        // 20480
#define RTOT_  (SHOFF_ + T_)    // 28672

// GEMM tiling
#define BM 128
#define BN 128
#define BK 32
#define ASTRIDE 36              // floats; ldmatrix rows land on disjoint bank-quads
#define BSTRIDE 136             // floats; conflict-free B frag reads
#define AS_BYTES (BM*ASTRIDE*4)     // 18432
#define BS_BYTES (BK*BSTRIDE*4)     // 17408
#define STAGE_BYTES (AS_BYTES + BS_BYTES)   // 35840
#define NSTAGE 3
#define SMEM_TOTAL (NSTAGE*STAGE_BYTES)     // 107520

// ---------------- scratch ----------------
__device__ int   g_flat_e[T_*2];
__device__ float g_flat_w[T_*2];
__device__ int   g_tok_all[RTOT_];
__device__ int   g_tok2gr[T_*2];
__device__ int   g_cnt[E_+1];
__device__ float g_big[(size_t)RTOT_*HID_];   // ada (stride 3072) then h1 (stride 4096)
__device__ float g_hy [(size_t)RTOT_*D_];     // h_mod then y
__device__ float g_gate[(size_t)RTOT_*D_];
__device__ float g_condg[(size_t)RTOT_*DC_];  // gathered + tf32-rounded cond

// ---------------- helpers ----------------
__device__ __forceinline__ uint32_t smem_u32(const void* p){
    uint32_t a;
    asm("{ .reg .u64 t; cvta.to.shared.u64 t, %1; cvt.u32.u64 %0, t; }" : "=r"(a) : "l"(p));
    return a;
}
__device__ __forceinline__ float totf32(float x){
    uint32_t u;
    asm("cvt.rn.tf32.f32 %0, %1;" : "=r"(u) : "f"(x));
    return __uint_as_float(u);
}
__device__ __forceinline__ uint32_t totf32u(float x){
    uint32_t u;
    asm("cvt.rn.tf32.f32 %0, %1;" : "=r"(u) : "f"(x));
    return u;
}
__device__ __forceinline__ float gelu_tanh(float x){
    float x3 = x*x*x;
    return 0.5f*x*(1.0f + tanhf(0.7978845608028654f*(x + 0.044715f*x3)));
}
__device__ __forceinline__ void cp16(uint32_t dst, const void* src){
    asm volatile("cp.async.cg.shared.global [%0], [%1], 16;" :: "r"(dst), "l"(src) : "memory");
}
__device__ __forceinline__ void cp_commit(){
    asm volatile("cp.async.commit_group;" ::: "memory");
}
__device__ __forceinline__ void ldsm4(uint32_t* r, uint32_t addr){
    asm volatile("ldmatrix.sync.aligned.m8n8.x4.shared.b16 {%0,%1,%2,%3}, [%4];"
                 : "=r"(r[0]), "=r"(r[1]), "=r"(r[2]), "=r"(r[3]) : "r"(addr));
}
__device__ __forceinline__ void mma_tf32(float* c, const uint32_t* a, const uint32_t* b){
    asm volatile("mma.sync.aligned.m16n8k8.row.col.f32.tf32.tf32.f32 "
                 "{%0,%1,%2,%3}, {%4,%5,%6,%7}, {%8,%9}, {%0,%1,%2,%3};"
                 : "+f"(c[0]), "+f"(c[1]), "+f"(c[2]), "+f"(c[3])
                 : "r"(a[0]), "r"(a[1]), "r"(a[2]), "r"(a[3]), "r"(b[0]), "r"(b[1]));
}

// ---------------- K1: router ----------------
__global__ void router_kernel(const float* __restrict__ x, const float* __restrict__ Wg){
    int t    = blockIdx.x*8 + (threadIdx.x>>5);
    int lane = threadIdx.x & 31;
    const float* xr = x + (size_t)t*D_;
    float s[NE_];
    #pragma unroll
    for (int j=0;j<NE_;j++) s[j]=0.f;
    for (int d=lane; d<D_; d+=32){
        float xv = xr[d];
        const float* wr = Wg + d*NE_;
        #pragma unroll
        for (int j=0;j<NE_;j++) s[j] += xv*wr[j];
    }
    #pragma unroll
    for (int o=16;o>0;o>>=1){
        #pragma unroll
        for (int j=0;j<NE_;j++) s[j] += __shfl_xor_sync(0xffffffffu, s[j], o);
    }
    if (lane==0){
        float mx = s[0];
        #pragma unroll
        for (int j=1;j<NE_;j++) mx = fmaxf(mx, s[j]);
        float p[NE_]; float sum=0.f;
        #pragma unroll
        for (int j=0;j<NE_;j++){ p[j]=expf(s[j]-mx); sum+=p[j]; }
        float inv = 1.f/sum;
        #pragma unroll
        for (int j=0;j<NE_;j++) p[j]*=inv;
        int i0=0; float p0=p[0];
        #pragma unroll
        for (int j=1;j<NE_;j++) if (p[j]>p0){p0=p[j]; i0=j;}
        int i1=-1; float p1=-1.f;
        #pragma unroll
        for (int j=0;j<NE_;j++) if (j!=i0 && p[j]>p1){p1=p[j]; i1=j;}
        float ws = p0+p1;
        g_flat_e[2*t]   = i0;  g_flat_e[2*t+1] = i1;
        g_flat_w[2*t]   = p0/ws;
        g_flat_w[2*t+1] = p1/ws;
    }
}

// ---------------- K2: stable binning (single block) ----------------
__global__ void bin_kernel(){
    __shared__ int hist[256][E_];
    const int tid = threadIdx.x;
    const int L = (T_*2)/256;
    const int lo = tid*L, hi = lo+L;
    int h[E_];
    #pragma unroll
    for (int e=0;e<E_;e++) h[e]=0;
    for (int i=lo;i<hi;i++) h[g_flat_e[i]]++;
    #pragma unroll
    for (int e=0;e<E_;e++) hist[tid][e]=h[e];
    __syncthreads();
    if (tid < E_){
        int run=0;
        for (int tt=0;tt<256;tt++){ int v=hist[tt][tid]; hist[tt][tid]=run; run+=v; }
        g_cnt[tid] = run < CAP_ ? run : CAP_;
    }
    if (tid == E_) g_cnt[E_] = T_;
    __syncthreads();
    int run[E_];
    #pragma unroll
    for (int e=0;e<E_;e++) run[e]=hist[tid][e];
    for (int i=lo;i<hi;i++){
        int e = g_flat_e[i];
        int rank = run[e]++;
        int gr = -1;
        if (rank < CAP_){ gr = e*CAP_ + rank; g_tok_all[gr] = i>>1; }
        g_tok2gr[i] = gr;
    }
    for (int t=tid; t<T_; t+=256) g_tok_all[SHOFF_+t] = t;
}

// ---------------- K3: gather cond (tf32-rounded) ----------------
__global__ void gather_cond_kernel(const float* __restrict__ cond){
    int gr = blockIdx.x;
    if (gr < SHOFF_){ int e = gr/CAP_; if ((gr - e*CAP_) >= g_cnt[e]) return; }
    int tok = g_tok_all[gr];
    const float4* src = (const float4*)(cond + (size_t)tok*DC_);
    float4* dst = (float4*)(g_condg + (size_t)gr*DC_);
    float4 v = src[threadIdx.x];
    v.x=totf32(v.x); v.y=totf32(v.y); v.z=totf32(v.z); v.w=totf32(v.w);
    dst[threadIdx.x] = v;
}

// ---------------- GEMM: mma.sync tf32, BK=32, ldmatrix A, 3-stage cp.async ----------------
// EPI: 0=ada raw store, 1=tf32(gelu)->h1, 2=*gate*mask -> y
// ASRC: 0=g_condg, 1=g_hy (h_mod, pre-rounded), 2=g_big (h1, pre-rounded)
template<int EPI, int ASRC>
__global__ void __launch_bounds__(256,2) gemm_mma(
    int K, int N,
    const float* __restrict__ Bw_e, const float* __restrict__ Bw_s,
    const float* __restrict__ bias_e, const float* __restrict__ bias_s,
    const float* __restrict__ mf)
{
    const int e   = blockIdx.z;
    const int cnt = g_cnt[e];
    const int m0  = blockIdx.y*BM;
    if (m0 >= cnt) return;
    const int row_off = (e < E_) ? e*CAP_ : SHOFF_;
    const float* Bw   = (e < E_) ? Bw_e   + (size_t)e*K*N : Bw_s;
    const float* bias = (e < E_) ? bias_e + (size_t)e*N   : bias_s;
    const float* Ap   = (ASRC==0) ? g_condg : (ASRC==1) ? g_hy : g_big;
    float* Cp         = (EPI==2) ? g_hy : g_big;

    const int n0  = blockIdx.x*BN;
    const int tid = threadIdx.x;
    const int lane = tid&31, wid = tid>>5;

    extern __shared__ char smem[];
    const uint32_t sbase = smem_u32(smem);

    // A loader: row = tid>>1 (0..127), k-half = (tid&1)*16, 4x cp16 at +{0,4,8,12}
    const int ar = tid>>1, ah = (tid&1)*16;
    int r_eff = m0 + ar; if (r_eff > cnt-1) r_eff = cnt-1;
    const float* Arow = Ap + (size_t)(row_off + r_eff)*K + ah;
    const uint32_t aDst = sbase + (uint32_t)(ar*ASTRIDE + ah)*4u;

    // B loader: k = (tid>>5) + 8j (j=0..3), n = (tid&31)*4, 4x cp16
    const int bk = tid>>5, bn = (tid&31)*4;
    const float* Bb = Bw + (size_t)bk*N + n0 + bn;
    const uint32_t bDst = sbase + AS_BYTES + (uint32_t)(bk*BSTRIDE + bn)*4u;

    // warp tile: 2 (M) x 4 (N) warps; each warp 64x32
    const int wm = (wid>>2)*64, wn = (wid&3)*32;
    const int g = lane>>2, tg = lane&3;

    // ldmatrix source row/col per lane (within the warp's A tile)
    const int lrow = lane&15, lcol = (lane>>4)*4;

    float acc[4][4][4];
    #pragma unroll
    for (int mt=0;mt<4;mt++)
        #pragma unroll
        for (int nt=0;nt<4;nt++)
            #pragma unroll
            for (int i=0;i<4;i++) acc[mt][nt][i]=0.f;

    const int KT = K/BK;

    // prologue: stages 0,1
    #pragma unroll
    for (int s=0;s<2;s++){
        const uint32_t so = s*STAGE_BYTES;
        const float* Ag = Arow + s*BK;
        const float* Bg = Bb   + (size_t)s*BK*N;
        #pragma unroll
        for (int j=0;j<4;j++){
            cp16(aDst+so+16u*j, Ag + 4*j);
            cp16(bDst+so+(uint32_t)(8*j*BSTRIDE)*4u, Bg + (size_t)(8*j)*N);
        }
        cp_commit();
    }

    for (int kt=0; kt<KT; kt++){
        if (kt+1<KT) asm volatile("cp.async.wait_group 1;" ::: "memory");
        else         asm volatile("cp.async.wait_group 0;" ::: "memory");
        __syncthreads();
        if (kt+2<KT){
            const int s2 = (kt+2)%NSTAGE;
            const uint32_t so = s2*STAGE_BYTES;
            const float* Ag = Arow + (kt+2)*BK;
            const float* Bg = Bb   + (size_t)(kt+2)*BK*N;
            #pragma unroll
            for (int j=0;j<4;j++){
                cp16(aDst+so+16u*j, Ag + 4*j);
                cp16(bDst+so+(uint32_t)(8*j*BSTRIDE)*4u, Bg + (size_t)(8*j)*N);
            }
            cp_commit();
        }
        const uint32_t aBase = sbase + (uint32_t)((kt%NSTAGE)*STAGE_BYTES);
        const float* Bs_ = (const float*)(smem + (kt%NSTAGE)*STAGE_BYTES + AS_BYTES);
        #pragma unroll
        for (int kk=0;kk<BK;kk+=8){
            uint32_t a[4][4], b[4][2];
            #pragma unroll
            for (int mt=0;mt<4;mt++){
                const uint32_t addr = aBase +
                    (uint32_t)(((wm + mt*16 + lrow)*ASTRIDE + kk + lcol)*4);
                ldsm4(a[mt], addr);
            }
            #pragma unroll
            for (int nt=0;nt<4;nt++){
                const int n = wn + nt*8 + g;
                b[nt][0]=totf32u(Bs_[(size_t)(kk+tg  )*BSTRIDE + n]);
                b[nt][1]=totf32u(Bs_[(size_t)(kk+tg+4)*BSTRIDE + n]);
            }
            #pragma unroll
            for (int mt=0;mt<4;mt++)
                #pragma unroll
                for (int nt=0;nt<4;nt++)
                    mma_tf32(acc[mt][nt], a[mt], b[nt]);
        }
        __syncthreads();
    }

    // epilogue
    #pragma unroll
    for (int mt=0;mt<4;mt++){
        #pragma unroll
        for (int half=0;half<2;half++){
            const int r = m0 + wm + mt*16 + g + half*8;
            if (r >= cnt) continue;
            const int gr = row_off + r;
            float msk = 1.f;
            if (EPI==2) msk = mf[g_tok_all[gr]];
            #pragma unroll
            for (int nt=0;nt<4;nt++){
                const int c = n0 + wn + nt*8 + 2*tg;
                float v0 = acc[mt][nt][half*2+0] + bias[c];
                float v1 = acc[mt][nt][half*2+1] + bias[c+1];
                if (EPI==1){ v0 = totf32(gelu_tanh(v0)); v1 = totf32(gelu_tanh(v1)); }
                if (EPI==2){
                    v0 = v0 * g_gate[(size_t)gr*N + c]   * msk;
                    v1 = v1 * g_gate[(size_t)gr*N + c+1] * msk;
                }
                *(float2*)&Cp[(size_t)gr*N + c] = make_float2(v0, v1);
            }
        }
    }
}

// ---------------- K4: LayerNorm + adaLN modulate (h_mod pre-rounded) ----------------
__global__ void hmod_kernel(const float* __restrict__ x){
    const int gr  = blockIdx.x;
    const int tid = threadIdx.x;
    if (gr < SHOFF_){
        int e = gr / CAP_;
        if ((gr - e*CAP_) >= g_cnt[e]) return;
    }
    const int tok = g_tok_all[gr];
    const float* xr = x + (size_t)tok*D_;
    float s=0.f, ss=0.f;
    for (int c=tid;c<D_;c+=256){ float v=xr[c]; s+=v; ss+=v*v; }
    #pragma unroll
    for (int o=16;o>0;o>>=1){
        s  += __shfl_xor_sync(0xffffffffu, s, o);
        ss += __shfl_xor_sync(0xffffffffu, ss, o);
    }
    __shared__ float sw[8], ssw[8];
    __shared__ float mu_s, rstd_s;
    const int w = tid>>5;
    if ((tid&31)==0){ sw[w]=s; ssw[w]=ss; }
    __syncthreads();
    if (tid==0){
        float S=0.f, SS=0.f;
        #pragma unroll
        for (int i=0;i<8;i++){ S+=sw[i]; SS+=ssw[i]; }
        float mu  = S*(1.f/(float)D_);
        float var = SS*(1.f/(float)D_) - mu*mu;
        mu_s = mu; rstd_s = rsqrtf(var + 1e-5f);
    }
    __syncthreads();
    const float mu = mu_s, rstd = rstd_s;
    const float* ada = g_big + (size_t)gr*(3*D_);
    float* hm = g_hy   + (size_t)gr*D_;
    float* gt = g_gate + (size_t)gr*D_;
    for (int c=tid;c<D_;c+=256){
        float xn = (xr[c]-mu)*rstd;
        hm[c] = totf32(xn*(1.f + ada[D_+c]) + ada[c]);
        gt[c] = ada[2*D_+c];
    }
}

// ---------------- K7: combine ----------------
__global__ void combine_kernel(float* __restrict__ out){
    const int idx = blockIdx.x*256 + threadIdx.x;
    const int t = idx >> 10;
    const int c = idx & (D_-1);
    float v = g_hy[(size_t)(SHOFF_+t)*D_ + c];
    const int gr0 = g_tok2gr[2*t];
    const int gr1 = g_tok2gr[2*t+1];
    float m = 0.f;
    if (gr0 >= 0) m += g_flat_w[2*t]   * g_hy[(size_t)gr0*D_ + c];
    if (gr1 >= 0) m += g_flat_w[2*t+1] * g_hy[(size_t)gr1*D_ + c];
    out[idx] = (v + 2.f*m) * (1.f/3.f);
}

// ---------------- launch ----------------
extern "C" void kernel_launch(void* const* d_in, const int* in_sizes, int n_in,
                              void* d_out, int out_size)
{
    const float* x      = (const float*)d_in[0];
    const float* cond   = (const float*)d_in[1];
    const float* mask   = (const float*)d_in[2];
    const float* Wg     = (const float*)d_in[3];
    const float* Wada_s = (const float*)d_in[4];
    const float* bada_s = (const float*)d_in[5];
    const float* W1_s   = (const float*)d_in[6];
    const float* b1_s   = (const float*)d_in[7];
    const float* W2_s   = (const float*)d_in[8];
    const float* b2_s   = (const float*)d_in[9];
    const float* Wada_e = (const float*)d_in[10];
    const float* bada_e = (const float*)d_in[11];
    const float* W1_e   = (const float*)d_in[12];
    const float* b1_e   = (const float*)d_in[13];
    const float* W2_e   = (const float*)d_in[14];
    const float* b2_e   = (const float*)d_in[15];
    float* out = (float*)d_out;

    cudaFuncSetAttribute(gemm_mma<0,0>, cudaFuncAttributeMaxDynamicSharedMemorySize, SMEM_TOTAL);
    cudaFuncSetAttribute(gemm_mma<1,1>, cudaFuncAttributeMaxDynamicSharedMemorySize, SMEM_TOTAL);
    cudaFuncSetAttribute(gemm_mma<2,2>, cudaFuncAttributeMaxDynamicSharedMemorySize, SMEM_TOTAL);

    router_kernel<<<T_/8, 256>>>(x, Wg);
    bin_kernel<<<1, 256>>>();
    gather_cond_kernel<<<RTOT_, 64>>>(cond);

    // ada = cond_g @ Wada + bada   (K=256, N=3072)
    gemm_mma<0,0><<<dim3(24,64,9),256,SMEM_TOTAL>>>(DC_, 3*D_, Wada_e, Wada_s, bada_e, bada_s, nullptr);

    hmod_kernel<<<RTOT_, 256>>>(x);

    // h1 = tf32(gelu(h_mod @ W1 + b1))   (K=1024, N=4096)
    gemm_mma<1,1><<<dim3(32,64,9),256,SMEM_TOTAL>>>(D_, HID_, W1_e, W1_s, b1_e, b1_s, nullptr);

    // y = (h1 @ W2 + b2) * gate * mask   (K=4096, N=1024)
    gemm_mma<2,2><<<dim3(8,64,9),256,SMEM_TOTAL>>>(HID_, D_, W2_e, W2_s, b2_e, b2_s, mask);

    combine_kernel<<<(T_*D_)/256, 256>>>(out);
}